// round 14
// baseline (speedup 1.0000x reference)
#include <cuda_runtime.h>
#include <cuda_bf16.h>
#include <math.h>
#include <stdint.h>

#define NN 50000
#define NE 800000
#define DIN 128
#define HID 192
#define SCAN_BLKS 196

// ---- scratch (device globals; allocation APIs are forbidden) ----
__device__ float g_h[NN * HID];
__device__ float g_m[NN * HID];
__device__ float g_p2[NN * 96];
__device__ float g_r[NN * 96];
__device__ float g_dinv[NN];
__device__ int   g_degi[NN];
__device__ int   g_cur[NN];
__device__ int   g_off[NN + 1];
__device__ int   g_csr_src[NE];
__device__ float g_csr_w[NE];
__device__ int   g_bsum[SCAN_BLKS];
__device__ int   g_boff[SCAN_BLKS];

__device__ __nv_bfloat16 g_x_hi[NN * DIN], g_x_lo[NN * DIN];
__device__ __nv_bfloat16 g_h_hi[NN * HID], g_h_lo[NN * HID];
__device__ __nv_bfloat16 g_p_hi[NN * HID], g_p_lo[NN * HID];

#define OW_P    0
#define OW_CONV 24576
#define OW_P1   172032
#define OW_P2   208896
#define OW_R1   227328
#define OW_TOT  245760
__device__ __nv_bfloat16 g_wt_hi[OW_TOT], g_wt_lo[OW_TOT];

// ---------------------------------------------------------------------------
// Degree / CSR construction
// ---------------------------------------------------------------------------
__global__ void deg_count_kernel(const int* __restrict__ dst) {
    int e = blockIdx.x * blockDim.x + threadIdx.x;
    if (e < NE) atomicAdd(&g_degi[dst[e]], 1);
}
// per-block exclusive scan; also computes dinv (degi is already in-register)
__global__ void scan1_kernel() {
    __shared__ int s[256];
    int tid = threadIdx.x;
    int i = blockIdx.x * 256 + tid;
    int v = (i < NN) ? g_degi[i] : 0;
    if (i < NN) g_dinv[i] = rsqrtf((float)(v + 1));   // +1 self-loop
    s[tid] = v;
    __syncthreads();
    #pragma unroll
    for (int off = 1; off < 256; off <<= 1) {
        int t = (tid >= off) ? s[tid - off] : 0;
        __syncthreads();
        s[tid] += t;
        __syncthreads();
    }
    if (i < NN) g_off[i] = s[tid] - v;
    if (tid == 255) g_bsum[blockIdx.x] = s[255];
}
__global__ void scan2_kernel() {
    __shared__ int s[256];
    int tid = threadIdx.x;
    int v = (tid < SCAN_BLKS) ? g_bsum[tid] : 0;
    s[tid] = v;
    __syncthreads();
    #pragma unroll
    for (int off = 1; off < 256; off <<= 1) {
        int t = (tid >= off) ? s[tid - off] : 0;
        __syncthreads();
        s[tid] += t;
        __syncthreads();
    }
    if (tid < SCAN_BLKS) g_boff[tid] = s[tid] - v;
    if (tid == 0) g_off[NN] = s[255];
}
__global__ void scan3_kernel() {
    int i = blockIdx.x * 256 + threadIdx.x;
    if (i < NN) g_off[i] += g_boff[blockIdx.x];
}
__global__ void csr_fill_kernel(const int* __restrict__ src, const int* __restrict__ dst) {
    int e = blockIdx.x * blockDim.x + threadIdx.x;
    if (e >= NE) return;
    int s = src[e], d = dst[e];
    int pos = g_off[d] + atomicAdd(&g_cur[d], 1);
    g_csr_src[pos] = s;
    g_csr_w[pos] = g_dinv[s] * g_dinv[d];
}

// ---------------------------------------------------------------------------
// Operand prep
// ---------------------------------------------------------------------------
__global__ void split_kernel(const float* __restrict__ in,
                             __nv_bfloat16* __restrict__ oh,
                             __nv_bfloat16* __restrict__ ol, int n) {
    int i = blockIdx.x * blockDim.x + threadIdx.x;
    if (i >= n) return;
    float v = in[i];
    __nv_bfloat16 h = __float2bfloat16(v);
    oh[i] = h;
    ol[i] = __float2bfloat16(v - __bfloat162float(h));
}

// weights transpose+split; also zeroes the CSR counters (merged launch)
__global__ void wprep_kernel(const float* __restrict__ Wp,
                             const float* __restrict__ convW,
                             const float* __restrict__ Wp1,
                             const float* __restrict__ Wp2,
                             const float* __restrict__ Wr1) {
    int idx = blockIdx.x * blockDim.x + threadIdx.x;
    if (idx < NN) { g_degi[idx] = 0; g_cur[idx] = 0; }
    if (idx >= OW_TOT) return;
    const float* src;
    int K, N, rel;
    if (idx < OW_CONV)      { rel = idx - OW_P;    src = Wp;  K = DIN; N = HID; }
    else if (idx < OW_P1)   { rel = idx - OW_CONV; src = convW + (rel / (HID * HID)) * (HID * HID);
                              rel %= HID * HID;    K = HID; N = HID; }
    else if (idx < OW_P2)   { rel = idx - OW_P1;   src = Wp1; K = HID; N = HID; }
    else if (idx < OW_R1)   { rel = idx - OW_P2;   src = Wp2; K = HID; N = 96;  }
    else                    { rel = idx - OW_R1;   src = Wr1; K = HID; N = 96;  }
    int n = rel / K, k = rel % K;
    float v = src[(size_t)k * N + n];
    __nv_bfloat16 h = __float2bfloat16(v);
    g_wt_hi[idx] = h;
    g_wt_lo[idx] = __float2bfloat16(v - __bfloat162float(h));
}

// ---------------------------------------------------------------------------
// Split-bf16 tensor-core GEMM — EXACT R11 configuration (proven 565us total).
// SW128 XOR-swizzled smem, 3-stage cp.async pipeline, 64-row tiles,
// 256 thr / 8 warps, 2 CTAs/SM.
// Row layout (128B): [hi cols 0..31 | lo cols 0..31], chunk c' = c ^ (r&7).
// C[M,N] = (Ah+Al)[M,K] @ (Bh+Bl)^T (B as [N,K]); Ah*Bh + Ah*Bl + Al*Bh.
// ---------------------------------------------------------------------------
#define MMA_BF16(d, a, b0_, b1_)                                              \
    asm volatile("mma.sync.aligned.m16n8k16.row.col.f32.bf16.bf16.f32 "       \
        "{%0,%1,%2,%3}, {%4,%5,%6,%7}, {%8,%9}, {%0,%1,%2,%3};"               \
        : "+f"((d)[0]), "+f"((d)[1]), "+f"((d)[2]), "+f"((d)[3])              \
        : "r"((a)[0]), "r"((a)[1]), "r"((a)[2]), "r"((a)[3]),                 \
          "r"(b0_), "r"(b1_))

#define LDSM_X4(r0, r1, r2, r3, addr)                                         \
    asm volatile("ldmatrix.sync.aligned.m8n8.x4.shared.b16 {%0,%1,%2,%3}, [%4];" \
        : "=r"(r0), "=r"(r1), "=r"(r2), "=r"(r3) : "r"(addr))

#define CP_A16(dst, src)                                                      \
    asm volatile("cp.async.cg.shared.global [%0], [%1], 16;"                  \
        :: "r"(dst), "l"(src))
#define CP_COMMIT() asm volatile("cp.async.commit_group;" ::: "memory")
#define CP_WAIT2()  asm volatile("cp.async.wait_group 2;" ::: "memory")
#define CP_WAIT1()  asm volatile("cp.async.wait_group 1;" ::: "memory")
#define CP_WAIT0()  asm volatile("cp.async.wait_group 0;" ::: "memory")

__device__ __forceinline__ uint32_t cvta_s(const void* p) {
    uint32_t a;
    asm("{ .reg .u64 t; cvta.to.shared.u64 t, %1; cvt.u32.u64 %0, t; }"
        : "=r"(a) : "l"(p));
    return a;
}

__device__ __forceinline__ void store_pair(
    float* Cf, __nv_bfloat16* Ch, __nv_bfloat16* Cl,
    size_t idx, float v0, float v1)
{
    if (Cf) *(float2*)(Cf + idx) = make_float2(v0, v1);
    if (Ch) {
        __nv_bfloat16 h0 = __float2bfloat16(v0), h1 = __float2bfloat16(v1);
        __nv_bfloat162 hp; hp.x = h0; hp.y = h1;
        *(__nv_bfloat162*)(Ch + idx) = hp;
        __nv_bfloat162 lp;
        lp.x = __float2bfloat16(v0 - __bfloat162float(h0));
        lp.y = __float2bfloat16(v1 - __bfloat162float(h1));
        *(__nv_bfloat162*)(Cl + idx) = lp;
    }
}

template <int N, int MW, int NW, int T>
__global__ __launch_bounds__(T, 2) void gemm_tc(
    const __nv_bfloat16* __restrict__ Ah, const __nv_bfloat16* __restrict__ Al,
    const __nv_bfloat16* __restrict__ Bh, const __nv_bfloat16* __restrict__ Bl,
    const float* __restrict__ bias, int relu,
    float* __restrict__ Cf, __nv_bfloat16* __restrict__ Ch,
    __nv_bfloat16* __restrict__ Cl, int M, int K)
{
    const int TM = 64;
    const int MF = TM / (16 * MW);
    const int NF = N / (8 * NW);
    const int A_BYTES = TM * 128;
    const int B_BYTES = N * 128;
    const int STAGE = A_BYTES + B_BYTES;
    const int NSTAGE = 3;

    extern __shared__ char smem[];
    uint32_t smem_u = cvta_s(smem);

    int tid = threadIdx.x, w = tid >> 5, lane = tid & 31;
    int row0 = blockIdx.x * TM;
    int mbase = (w % MW) * (MF * 16);
    int nbase = (w / MW) * (NF * 8);
    int lr = lane >> 2;
    int lc = (lane & 3) * 2;
    int lane7 = lane & 7;

    uint32_t aRow = (uint32_t)(((lane & 7) + 8 * ((lane >> 3) & 1)) * 128);
    uint32_t aC   = (uint32_t)(lane >> 4);
    uint32_t bRow = (uint32_t)(((lane & 7) + 8 * (lane >> 4)) * 128);
    uint32_t bC   = (uint32_t)((lane >> 3) & 1);

    float acc[MF][NF][4];
    #pragma unroll
    for (int a = 0; a < MF; a++)
        #pragma unroll
        for (int b = 0; b < NF; b++)
            #pragma unroll
            for (int c = 0; c < 4; c++) acc[a][b][c] = 0.0f;

    int nkc = K >> 5;

    auto load_tiles = [&](int st, int kc) {
        uint32_t base = smem_u + (uint32_t)(st * STAGE);
        for (int u = tid; u < TM * 8; u += T) {
            int r = u >> 3, c = u & 7;
            int gr = row0 + r;
            uint32_t dst = base + (uint32_t)(r << 7) + (uint32_t)(((c ^ (r & 7)) << 4));
            if (gr < M) {
                const __nv_bfloat16* s =
                    (c < 4 ? Ah : Al) + (size_t)gr * K + kc * 32 + (c & 3) * 8;
                CP_A16(dst, s);
            } else {
                asm volatile("st.shared.v4.b32 [%0], {%1,%1,%1,%1};"
                             :: "r"(dst), "r"(0u) : "memory");
            }
        }
        uint32_t bbase = base + (uint32_t)A_BYTES;
        for (int u = tid; u < N * 8; u += T) {
            int r = u >> 3, c = u & 7;
            uint32_t dst = bbase + (uint32_t)(r << 7) + (uint32_t)(((c ^ (r & 7)) << 4));
            const __nv_bfloat16* s =
                (c < 4 ? Bh : Bl) + (size_t)r * K + kc * 32 + (c & 3) * 8;
            CP_A16(dst, s);
        }
        CP_COMMIT();
    };

    int issued = 0;
    for (; issued < NSTAGE - 1 && issued < nkc; issued++)
        load_tiles(issued % NSTAGE, issued);

    for (int kc = 0; kc < nkc; kc++) {
        if (issued < nkc) { load_tiles(issued % NSTAGE, issued); issued++; }
        int pend = issued - kc - 1;
        if (pend >= 2) CP_WAIT2();
        else if (pend == 1) CP_WAIT1();
        else CP_WAIT0();
        __syncthreads();

        uint32_t aBase = smem_u + (uint32_t)((kc % NSTAGE) * STAGE);
        uint32_t bBase = aBase + (uint32_t)A_BYTES;

        #pragma unroll
        for (int ks = 0; ks < 2; ks++) {
            int c0h = 2 * ks;
            int c0l = 4 + 2 * ks;
            uint32_t ahf[MF][4], alf[MF][4];
            #pragma unroll
            for (int mf = 0; mf < MF; mf++) {
                uint32_t rowb = aBase + (uint32_t)((mbase + mf * 16) << 7) + aRow;
                LDSM_X4(ahf[mf][0], ahf[mf][1], ahf[mf][2], ahf[mf][3],
                        rowb + (uint32_t)((((int)(c0h + aC) ^ lane7) << 4)));
                LDSM_X4(alf[mf][0], alf[mf][1], alf[mf][2], alf[mf][3],
                        rowb + (uint32_t)((((int)(c0l + aC) ^ lane7) << 4)));
            }
            #pragma unroll
            for (int nf2 = 0; nf2 < NF / 2; nf2++) {
                uint32_t rowb = bBase + (uint32_t)((nbase + nf2 * 16) << 7) + bRow;
                uint32_t bh[4], bl[4];
                LDSM_X4(bh[0], bh[1], bh[2], bh[3],
                        rowb + (uint32_t)((((int)(c0h + bC) ^ lane7) << 4)));
                LDSM_X4(bl[0], bl[1], bl[2], bl[3],
                        rowb + (uint32_t)((((int)(c0l + bC) ^ lane7) << 4)));
                #pragma unroll
                for (int mf = 0; mf < MF; mf++) {
                    MMA_BF16(acc[mf][2 * nf2],     ahf[mf], bh[0], bh[1]);
                    MMA_BF16(acc[mf][2 * nf2],     ahf[mf], bl[0], bl[1]);
                    MMA_BF16(acc[mf][2 * nf2],     alf[mf], bh[0], bh[1]);
                    MMA_BF16(acc[mf][2 * nf2 + 1], ahf[mf], bh[2], bh[3]);
                    MMA_BF16(acc[mf][2 * nf2 + 1], ahf[mf], bl[2], bl[3]);
                    MMA_BF16(acc[mf][2 * nf2 + 1], alf[mf], bh[2], bh[3]);
                }
            }
        }
        __syncthreads();
    }

    #pragma unroll
    for (int mf = 0; mf < MF; mf++) {
        int r0 = row0 + mbase + mf * 16 + lr;
        #pragma unroll
        for (int nf = 0; nf < NF; nf++) {
            int col = nbase + nf * 8 + lc;
            float b0 = 0.0f, b1 = 0.0f;
            if (bias) { b0 = bias[col]; b1 = bias[col + 1]; }
            float v0 = acc[mf][nf][0] + b0, v1 = acc[mf][nf][1] + b1;
            float v2 = acc[mf][nf][2] + b0, v3 = acc[mf][nf][3] + b1;
            if (relu) {
                v0 = fmaxf(v0, 0.f); v1 = fmaxf(v1, 0.f);
                v2 = fmaxf(v2, 0.f); v3 = fmaxf(v3, 0.f);
            }
            if (r0 < M)     store_pair(Cf, Ch, Cl, (size_t)r0 * N + col, v0, v1);
            if (r0 + 8 < M) store_pair(Cf, Ch, Cl, (size_t)(r0 + 8) * N + col, v2, v3);
        }
    }
}

// ---------------------------------------------------------------------------
// Fused GCN aggregation + residual + relu + bf16 split.
// Edge loop software-prefetches (src, w) of edge j+1 before the FMAs of j.
// ---------------------------------------------------------------------------
__device__ __forceinline__ void f4_fma(float4& a, float w, const float4 v) {
    a.x = fmaf(w, v.x, a.x); a.y = fmaf(w, v.y, a.y);
    a.z = fmaf(w, v.z, a.z); a.w = fmaf(w, v.w, a.w);
}
__device__ __forceinline__ void split_store4(size_t base, float4 v) {
    float vv[4] = {v.x, v.y, v.z, v.w};
    __nv_bfloat16 hh[4], ll[4];
    #pragma unroll
    for (int i = 0; i < 4; i++) {
        hh[i] = __float2bfloat16(vv[i]);
        ll[i] = __float2bfloat16(vv[i] - __bfloat162float(hh[i]));
    }
    *(uint2*)(g_h_hi + base) = *(uint2*)hh;
    *(uint2*)(g_h_lo + base) = *(uint2*)ll;
}

__global__ __launch_bounds__(256) void gcn_agg_kernel(const float* __restrict__ convB) {
    int t = blockIdx.x * blockDim.x + threadIdx.x;
    int node = t >> 4;
    int lane = t & 15;
    if (node >= NN) return;

    float di = g_dinv[node];
    float w0 = di * di;
    const float4* mrow = (const float4*)(g_m + (size_t)node * HID);
    float4 a0 = mrow[lane], a1 = mrow[lane + 16], a2 = mrow[lane + 32];
    a0.x *= w0; a0.y *= w0; a0.z *= w0; a0.w *= w0;
    a1.x *= w0; a1.y *= w0; a1.z *= w0; a1.w *= w0;
    a2.x *= w0; a2.y *= w0; a2.z *= w0; a2.w *= w0;

    int beg = g_off[node], end = g_off[node + 1];
    if (beg < end) {
        int s = g_csr_src[beg];
        float w = g_csr_w[beg];
        for (int j = beg; j < end; j++) {
            // prefetch next edge's metadata before the dependent row loads
            int sn = 0; float wn = 0.0f;
            if (j + 1 < end) { sn = g_csr_src[j + 1]; wn = g_csr_w[j + 1]; }
            const float4* ms = (const float4*)(g_m + (size_t)s * HID);
            f4_fma(a0, w, ms[lane]);
            f4_fma(a1, w, ms[lane + 16]);
            f4_fma(a2, w, ms[lane + 32]);
            s = sn; w = wn;
        }
    }

    const float4* b4 = (const float4*)convB;
    float4 b0 = b4[lane], b1 = b4[lane + 16], b2 = b4[lane + 32];
    float4* hrow = (float4*)(g_h + (size_t)node * HID);
    float4 h0 = hrow[lane], h1 = hrow[lane + 16], h2 = hrow[lane + 32];
    h0.x += fmaxf(a0.x + b0.x, 0.f); h0.y += fmaxf(a0.y + b0.y, 0.f);
    h0.z += fmaxf(a0.z + b0.z, 0.f); h0.w += fmaxf(a0.w + b0.w, 0.f);
    h1.x += fmaxf(a1.x + b1.x, 0.f); h1.y += fmaxf(a1.y + b1.y, 0.f);
    h1.z += fmaxf(a1.z + b1.z, 0.f); h1.w += fmaxf(a1.w + b1.w, 0.f);
    h2.x += fmaxf(a2.x + b2.x, 0.f); h2.y += fmaxf(a2.y + b2.y, 0.f);
    h2.z += fmaxf(a2.z + b2.z, 0.f); h2.w += fmaxf(a2.w + b2.w, 0.f);
    hrow[lane] = h0; hrow[lane + 16] = h1; hrow[lane + 32] = h2;

    size_t base = (size_t)node * HID + lane * 4;
    split_store4(base, h0);
    split_store4(base + 64, h1);
    split_store4(base + 128, h2);
}

// ---------------------------------------------------------------------------
// Final head (unchanged)
// ---------------------------------------------------------------------------
__global__ void head_final_kernel(
    const float* __restrict__ Wp3, const float* __restrict__ bp3,
    const float* __restrict__ Wr2, const float* __restrict__ br2,
    float* __restrict__ out)
{
    int w = (blockIdx.x * blockDim.x + threadIdx.x) >> 5;
    int lane = threadIdx.x & 31;
    if (w >= NN) return;
    const float* p2 = g_p2 + (size_t)w * 96;
    const float* rr = g_r + (size_t)w * 96;
    float a0 = 0.0f, a1 = 0.0f, ar = 0.0f;
    #pragma unroll
    for (int i = lane; i < 96; i += 32) {
        float v = p2[i];
        a0 = fmaf(v, Wp3[i * 2 + 0], a0);
        a1 = fmaf(v, Wp3[i * 2 + 1], a1);
        ar = fmaf(rr[i], Wr2[i], ar);
    }
    #pragma unroll
    for (int o = 16; o; o >>= 1) {
        a0 += __shfl_down_sync(0xFFFFFFFFu, a0, o);
        a1 += __shfl_down_sync(0xFFFFFFFFu, a1, o);
        ar += __shfl_down_sync(0xFFFFFFFFu, ar, o);
    }
    if (lane == 0) {
        float p0 = a0 + bp3[0];
        float p1 = a1 + bp3[1];
        float rad = 1.0f / (1.0f + expf(-(ar + br2[0])));
        float nrm = sqrtf(p0 * p0 + p1 * p1) + 1e-8f;
        float scale = rad / nrm;
        out[w * 2 + 0] = p0 * scale;
        out[w * 2 + 1] = p1 * scale;
    }
}

// ---------------------------------------------------------------------------
extern "C" void kernel_launch(void* const* d_in, const int* in_sizes, int n_in,
                              void* d_out, int out_size)
{
    const float *x, *Wp, *bp, *convW, *convB, *Wp1, *bp1, *Wp2, *bp2, *Wp3, *bp3;
    const float *Wr1, *br1, *Wr2, *br2;
    const int *ei;

    if (in_sizes[0] == NN * DIN) {
        x     = (const float*)d_in[0];
        ei    = (const int*)  d_in[1];
        Wp    = (const float*)d_in[2];  bp    = (const float*)d_in[3];
        convW = (const float*)d_in[4];  convB = (const float*)d_in[5];
        Wp1   = (const float*)d_in[6];  bp1   = (const float*)d_in[7];
        Wp2   = (const float*)d_in[8];  bp2   = (const float*)d_in[9];
        Wp3   = (const float*)d_in[10]; bp3   = (const float*)d_in[11];
        Wr1   = (const float*)d_in[12]; br1   = (const float*)d_in[13];
        Wr2   = (const float*)d_in[14]; br2   = (const float*)d_in[15];
    } else {
        Wp    = (const float*)d_in[0];
        Wp1   = (const float*)d_in[1];
        Wp2   = (const float*)d_in[2];
        Wp3   = (const float*)d_in[3];
        Wr1   = (const float*)d_in[4];
        Wr2   = (const float*)d_in[5];
        bp    = (const float*)d_in[6];
        bp1   = (const float*)d_in[7];
        bp2   = (const float*)d_in[8];
        bp3   = (const float*)d_in[9];
        br1   = (const float*)d_in[10];
        br2   = (const float*)d_in[11];
        convB = (const float*)d_in[12];
        convW = (const float*)d_in[13];
        ei    = (const int*)  d_in[14];
        x     = (const float*)d_in[15];
    }
    float* out = (float*)d_out;

    float *p_h, *p_m, *p_p2, *p_r;
    __nv_bfloat16 *p_xh, *p_xl, *p_hh, *p_hl, *p_ph, *p_pl, *p_wh, *p_wl;
    cudaGetSymbolAddress((void**)&p_h,  g_h);
    cudaGetSymbolAddress((void**)&p_m,  g_m);
    cudaGetSymbolAddress((void**)&p_p2, g_p2);
    cudaGetSymbolAddress((void**)&p_r,  g_r);
    cudaGetSymbolAddress((void**)&p_xh, g_x_hi);
    cudaGetSymbolAddress((void**)&p_xl, g_x_lo);
    cudaGetSymbolAddress((void**)&p_hh, g_h_hi);
    cudaGetSymbolAddress((void**)&p_hl, g_h_lo);
    cudaGetSymbolAddress((void**)&p_ph, g_p_hi);
    cudaGetSymbolAddress((void**)&p_pl, g_p_lo);
    cudaGetSymbolAddress((void**)&p_wh, g_wt_hi);
    cudaGetSymbolAddress((void**)&p_wl, g_wt_lo);

    const int* src = ei;
    const int* dst = ei + NE;

    int nblk = (NN + 63) / 64;   // 782
    size_t sm192 = (size_t)3 * (64 + 192) * 128;  // 98304
    size_t sm96  = (size_t)3 * (64 + 96)  * 128;  // 61440
    cudaFuncSetAttribute((const void*)gemm_tc<192, 2, 4, 256>,
                         cudaFuncAttributeMaxDynamicSharedMemorySize, (int)sm192);
    cudaFuncSetAttribute((const void*)gemm_tc<96, 4, 2, 256>,
                         cudaFuncAttributeMaxDynamicSharedMemorySize, (int)sm96);

    // --- launch order keeps the projection GEMM at profile idx 3 ---
    split_kernel<<<(NN * DIN + 255) / 256, 256>>>(x, p_xh, p_xl, NN * DIN);   // idx 0
    wprep_kernel<<<(OW_TOT + 255) / 256, 256>>>(Wp, convW, Wp1, Wp2, Wr1);    // idx 1 (+zero)
    deg_count_kernel<<<(NE + 255) / 256, 256>>>(dst);                         // idx 2
    gemm_tc<192, 2, 4, 256><<<nblk, 256, sm192>>>(p_xh, p_xl, p_wh + OW_P,    // idx 3
                                                  p_wl + OW_P, bp, 0, p_h, p_hh, p_hl,
                                                  NN, DIN);

    // CSR build (scan1 also computes dinv)
    scan1_kernel<<<SCAN_BLKS, 256>>>();
    scan2_kernel<<<1, 256>>>();
    scan3_kernel<<<SCAN_BLKS, 256>>>();
    csr_fill_kernel<<<(NE + 255) / 256, 256>>>(src, dst);

    // 4 GCN layers
    for (int l = 0; l < 4; l++) {
        gemm_tc<192, 2, 4, 256><<<nblk, 256, sm192>>>(p_hh, p_hl,
                                                      p_wh + OW_CONV + l * HID * HID,
                                                      p_wl + OW_CONV + l * HID * HID,
                                                      nullptr, 0, p_m, nullptr, nullptr,
                                                      NN, HID);
        gcn_agg_kernel<<<(NN * 16 + 255) / 256, 256>>>(convB + (size_t)l * HID);
    }

    // heads
    gemm_tc<192, 2, 4, 256><<<nblk, 256, sm192>>>(p_hh, p_hl, p_wh + OW_P1, p_wl + OW_P1,
                                                  bp1, 1, nullptr, p_ph, p_pl, NN, HID);
    gemm_tc<96, 4, 2, 256><<<nblk, 256, sm96>>>(p_ph, p_pl, p_wh + OW_P2, p_wl + OW_P2,
                                                bp2, 1, p_p2, nullptr, nullptr, NN, HID);
    gemm_tc<96, 4, 2, 256><<<nblk, 256, sm96>>>(p_hh, p_hl, p_wh + OW_R1, p_wl + OW_R1,
                                                br1, 1, p_r, nullptr, nullptr, NN, HID);
    head_final_kernel<<<(NN * 32 + 255) / 256, 256>>>(Wp3, bp3, Wr2, br2, out);
}

// round 15
// speedup vs baseline: 1.0442x; 1.0442x over previous
#include <cuda_runtime.h>
#include <cuda_bf16.h>
#include <math.h>
#include <stdint.h>

#define NN 50000
#define NE 800000
#define DIN 128
#define HID 192
#define SCAN_BLKS 196

// ---- scratch (device globals; allocation APIs are forbidden) ----
__device__ float g_h[NN * HID];
__device__ float g_m[NN * HID];
__device__ float g_p2[NN * 96];
__device__ float g_r[NN * 96];
__device__ float g_dinv[NN];
__device__ int   g_degi[NN];
__device__ int   g_cur[NN];
__device__ int   g_off[NN + 1];
__device__ int   g_csr_src[NE];
__device__ float g_csr_w[NE];
__device__ int   g_bsum[SCAN_BLKS];
__device__ int   g_boff[SCAN_BLKS];

__device__ __nv_bfloat16 g_x_hi[NN * DIN], g_x_lo[NN * DIN];
__device__ __nv_bfloat16 g_h_hi[NN * HID], g_h_lo[NN * HID];
__device__ __nv_bfloat16 g_p_hi[NN * HID], g_p_lo[NN * HID];

#define OW_P    0
#define OW_CONV 24576
#define OW_P1   172032
#define OW_P2   208896
#define OW_R1   227328
#define OW_TOT  245760
__device__ __nv_bfloat16 g_wt_hi[OW_TOT], g_wt_lo[OW_TOT];

// ---------------------------------------------------------------------------
// Degree / CSR construction (byte-identical to R11 kernels)
// ---------------------------------------------------------------------------
__global__ void zero_counts_kernel() {
    int i = blockIdx.x * blockDim.x + threadIdx.x;
    if (i < NN) { g_degi[i] = 0; g_cur[i] = 0; }
}
__global__ void deg_count_kernel(const int* __restrict__ dst) {
    int e = blockIdx.x * blockDim.x + threadIdx.x;
    if (e < NE) atomicAdd(&g_degi[dst[e]], 1);
}
__global__ void scan1_kernel() {
    __shared__ int s[256];
    int tid = threadIdx.x;
    int i = blockIdx.x * 256 + tid;
    int v = (i < NN) ? g_degi[i] : 0;
    s[tid] = v;
    __syncthreads();
    #pragma unroll
    for (int off = 1; off < 256; off <<= 1) {
        int t = (tid >= off) ? s[tid - off] : 0;
        __syncthreads();
        s[tid] += t;
        __syncthreads();
    }
    if (i < NN) g_off[i] = s[tid] - v;
    if (tid == 255) g_bsum[blockIdx.x] = s[255];
}
__global__ void scan2_kernel() {
    __shared__ int s[256];
    int tid = threadIdx.x;
    int v = (tid < SCAN_BLKS) ? g_bsum[tid] : 0;
    s[tid] = v;
    __syncthreads();
    #pragma unroll
    for (int off = 1; off < 256; off <<= 1) {
        int t = (tid >= off) ? s[tid - off] : 0;
        __syncthreads();
        s[tid] += t;
        __syncthreads();
    }
    if (tid < SCAN_BLKS) g_boff[tid] = s[tid] - v;
    if (tid == 0) g_off[NN] = s[255];
}
__global__ void scan3_kernel() {
    int i = blockIdx.x * 256 + threadIdx.x;
    if (i < NN) g_off[i] += g_boff[blockIdx.x];
}
__global__ void dinv_kernel() {
    int i = blockIdx.x * blockDim.x + threadIdx.x;
    if (i < NN) g_dinv[i] = rsqrtf((float)(g_degi[i] + 1));
}
__global__ void csr_fill_kernel(const int* __restrict__ src, const int* __restrict__ dst) {
    int e = blockIdx.x * blockDim.x + threadIdx.x;
    if (e >= NE) return;
    int s = src[e], d = dst[e];
    int pos = g_off[d] + atomicAdd(&g_cur[d], 1);
    g_csr_src[pos] = s;
    g_csr_w[pos] = g_dinv[s] * g_dinv[d];
}

// ---------------------------------------------------------------------------
// Operand prep (byte-identical to R11)
// ---------------------------------------------------------------------------
__global__ void split_kernel(const float* __restrict__ in,
                             __nv_bfloat16* __restrict__ oh,
                             __nv_bfloat16* __restrict__ ol, int n) {
    int i = blockIdx.x * blockDim.x + threadIdx.x;
    if (i >= n) return;
    float v = in[i];
    __nv_bfloat16 h = __float2bfloat16(v);
    oh[i] = h;
    ol[i] = __float2bfloat16(v - __bfloat162float(h));
}

__global__ void wprep_kernel(const float* __restrict__ Wp,
                             const float* __restrict__ convW,
                             const float* __restrict__ Wp1,
                             const float* __restrict__ Wp2,
                             const float* __restrict__ Wr1) {
    int idx = blockIdx.x * blockDim.x + threadIdx.x;
    if (idx >= OW_TOT) return;
    const float* src;
    int K, N, rel;
    if (idx < OW_CONV)      { rel = idx - OW_P;    src = Wp;  K = DIN; N = HID; }
    else if (idx < OW_P1)   { rel = idx - OW_CONV; src = convW + (rel / (HID * HID)) * (HID * HID);
                              rel %= HID * HID;    K = HID; N = HID; }
    else if (idx < OW_P2)   { rel = idx - OW_P1;   src = Wp1; K = HID; N = HID; }
    else if (idx < OW_R1)   { rel = idx - OW_P2;   src = Wp2; K = HID; N = 96;  }
    else                    { rel = idx - OW_R1;   src = Wr1; K = HID; N = 96;  }
    int n = rel / K, k = rel % K;
    float v = src[(size_t)k * N + n];
    __nv_bfloat16 h = __float2bfloat16(v);
    g_wt_hi[idx] = h;
    g_wt_lo[idx] = __float2bfloat16(v - __bfloat162float(h));
}

// ---------------------------------------------------------------------------
// Split-bf16 tensor-core GEMM — EXACT R11 configuration (banked 565us).
// ---------------------------------------------------------------------------
#define MMA_BF16(d, a, b0_, b1_)                                              \
    asm volatile("mma.sync.aligned.m16n8k16.row.col.f32.bf16.bf16.f32 "       \
        "{%0,%1,%2,%3}, {%4,%5,%6,%7}, {%8,%9}, {%0,%1,%2,%3};"               \
        : "+f"((d)[0]), "+f"((d)[1]), "+f"((d)[2]), "+f"((d)[3])              \
        : "r"((a)[0]), "r"((a)[1]), "r"((a)[2]), "r"((a)[3]),                 \
          "r"(b0_), "r"(b1_))

#define LDSM_X4(r0, r1, r2, r3, addr)                                         \
    asm volatile("ldmatrix.sync.aligned.m8n8.x4.shared.b16 {%0,%1,%2,%3}, [%4];" \
        : "=r"(r0), "=r"(r1), "=r"(r2), "=r"(r3) : "r"(addr))

#define CP_A16(dst, src)                                                      \
    asm volatile("cp.async.cg.shared.global [%0], [%1], 16;"                  \
        :: "r"(dst), "l"(src))
#define CP_COMMIT() asm volatile("cp.async.commit_group;" ::: "memory")
#define CP_WAIT2()  asm volatile("cp.async.wait_group 2;" ::: "memory")
#define CP_WAIT1()  asm volatile("cp.async.wait_group 1;" ::: "memory")
#define CP_WAIT0()  asm volatile("cp.async.wait_group 0;" ::: "memory")

__device__ __forceinline__ uint32_t cvta_s(const void* p) {
    uint32_t a;
    asm("{ .reg .u64 t; cvta.to.shared.u64 t, %1; cvt.u32.u64 %0, t; }"
        : "=r"(a) : "l"(p));
    return a;
}

__device__ __forceinline__ void store_pair(
    float* Cf, __nv_bfloat16* Ch, __nv_bfloat16* Cl,
    size_t idx, float v0, float v1)
{
    if (Cf) *(float2*)(Cf + idx) = make_float2(v0, v1);
    if (Ch) {
        __nv_bfloat16 h0 = __float2bfloat16(v0), h1 = __float2bfloat16(v1);
        __nv_bfloat162 hp; hp.x = h0; hp.y = h1;
        *(__nv_bfloat162*)(Ch + idx) = hp;
        __nv_bfloat162 lp;
        lp.x = __float2bfloat16(v0 - __bfloat162float(h0));
        lp.y = __float2bfloat16(v1 - __bfloat162float(h1));
        *(__nv_bfloat162*)(Cl + idx) = lp;
    }
}

template <int N, int MW, int NW, int T>
__global__ __launch_bounds__(T, 2) void gemm_tc(
    const __nv_bfloat16* __restrict__ Ah, const __nv_bfloat16* __restrict__ Al,
    const __nv_bfloat16* __restrict__ Bh, const __nv_bfloat16* __restrict__ Bl,
    const float* __restrict__ bias, int relu,
    float* __restrict__ Cf, __nv_bfloat16* __restrict__ Ch,
    __nv_bfloat16* __restrict__ Cl, int M, int K)
{
    const int TM = 64;
    const int MF = TM / (16 * MW);
    const int NF = N / (8 * NW);
    const int A_BYTES = TM * 128;
    const int B_BYTES = N * 128;
    const int STAGE = A_BYTES + B_BYTES;
    const int NSTAGE = 3;

    extern __shared__ char smem[];
    uint32_t smem_u = cvta_s(smem);

    int tid = threadIdx.x, w = tid >> 5, lane = tid & 31;
    int row0 = blockIdx.x * TM;
    int mbase = (w % MW) * (MF * 16);
    int nbase = (w / MW) * (NF * 8);
    int lr = lane >> 2;
    int lc = (lane & 3) * 2;
    int lane7 = lane & 7;

    uint32_t aRow = (uint32_t)(((lane & 7) + 8 * ((lane >> 3) & 1)) * 128);
    uint32_t aC   = (uint32_t)(lane >> 4);
    uint32_t bRow = (uint32_t)(((lane & 7) + 8 * (lane >> 4)) * 128);
    uint32_t bC   = (uint32_t)((lane >> 3) & 1);

    float acc[MF][NF][4];
    #pragma unroll
    for (int a = 0; a < MF; a++)
        #pragma unroll
        for (int b = 0; b < NF; b++)
            #pragma unroll
            for (int c = 0; c < 4; c++) acc[a][b][c] = 0.0f;

    int nkc = K >> 5;

    auto load_tiles = [&](int st, int kc) {
        uint32_t base = smem_u + (uint32_t)(st * STAGE);
        for (int u = tid; u < TM * 8; u += T) {
            int r = u >> 3, c = u & 7;
            int gr = row0 + r;
            uint32_t dst = base + (uint32_t)(r << 7) + (uint32_t)(((c ^ (r & 7)) << 4));
            if (gr < M) {
                const __nv_bfloat16* s =
                    (c < 4 ? Ah : Al) + (size_t)gr * K + kc * 32 + (c & 3) * 8;
                CP_A16(dst, s);
            } else {
                asm volatile("st.shared.v4.b32 [%0], {%1,%1,%1,%1};"
                             :: "r"(dst), "r"(0u) : "memory");
            }
        }
        uint32_t bbase = base + (uint32_t)A_BYTES;
        for (int u = tid; u < N * 8; u += T) {
            int r = u >> 3, c = u & 7;
            uint32_t dst = bbase + (uint32_t)(r << 7) + (uint32_t)(((c ^ (r & 7)) << 4));
            const __nv_bfloat16* s =
                (c < 4 ? Bh : Bl) + (size_t)r * K + kc * 32 + (c & 3) * 8;
            CP_A16(dst, s);
        }
        CP_COMMIT();
    };

    int issued = 0;
    for (; issued < NSTAGE - 1 && issued < nkc; issued++)
        load_tiles(issued % NSTAGE, issued);

    for (int kc = 0; kc < nkc; kc++) {
        if (issued < nkc) { load_tiles(issued % NSTAGE, issued); issued++; }
        int pend = issued - kc - 1;
        if (pend >= 2) CP_WAIT2();
        else if (pend == 1) CP_WAIT1();
        else CP_WAIT0();
        __syncthreads();

        uint32_t aBase = smem_u + (uint32_t)((kc % NSTAGE) * STAGE);
        uint32_t bBase = aBase + (uint32_t)A_BYTES;

        #pragma unroll
        for (int ks = 0; ks < 2; ks++) {
            int c0h = 2 * ks;
            int c0l = 4 + 2 * ks;
            uint32_t ahf[MF][4], alf[MF][4];
            #pragma unroll
            for (int mf = 0; mf < MF; mf++) {
                uint32_t rowb = aBase + (uint32_t)((mbase + mf * 16) << 7) + aRow;
                LDSM_X4(ahf[mf][0], ahf[mf][1], ahf[mf][2], ahf[mf][3],
                        rowb + (uint32_t)((((int)(c0h + aC) ^ lane7) << 4)));
                LDSM_X4(alf[mf][0], alf[mf][1], alf[mf][2], alf[mf][3],
                        rowb + (uint32_t)((((int)(c0l + aC) ^ lane7) << 4)));
            }
            #pragma unroll
            for (int nf2 = 0; nf2 < NF / 2; nf2++) {
                uint32_t rowb = bBase + (uint32_t)((nbase + nf2 * 16) << 7) + bRow;
                uint32_t bh[4], bl[4];
                LDSM_X4(bh[0], bh[1], bh[2], bh[3],
                        rowb + (uint32_t)((((int)(c0h + bC) ^ lane7) << 4)));
                LDSM_X4(bl[0], bl[1], bl[2], bl[3],
                        rowb + (uint32_t)((((int)(c0l + bC) ^ lane7) << 4)));
                #pragma unroll
                for (int mf = 0; mf < MF; mf++) {
                    MMA_BF16(acc[mf][2 * nf2],     ahf[mf], bh[0], bh[1]);
                    MMA_BF16(acc[mf][2 * nf2],     ahf[mf], bl[0], bl[1]);
                    MMA_BF16(acc[mf][2 * nf2],     alf[mf], bh[0], bh[1]);
                    MMA_BF16(acc[mf][2 * nf2 + 1], ahf[mf], bh[2], bh[3]);
                    MMA_BF16(acc[mf][2 * nf2 + 1], ahf[mf], bl[2], bl[3]);
                    MMA_BF16(acc[mf][2 * nf2 + 1], alf[mf], bh[2], bh[3]);
                }
            }
        }
        __syncthreads();
    }

    #pragma unroll
    for (int mf = 0; mf < MF; mf++) {
        int r0 = row0 + mbase + mf * 16 + lr;
        #pragma unroll
        for (int nf = 0; nf < NF; nf++) {
            int col = nbase + nf * 8 + lc;
            float b0 = 0.0f, b1 = 0.0f;
            if (bias) { b0 = bias[col]; b1 = bias[col + 1]; }
            float v0 = acc[mf][nf][0] + b0, v1 = acc[mf][nf][1] + b1;
            float v2 = acc[mf][nf][2] + b0, v3 = acc[mf][nf][3] + b1;
            if (relu) {
                v0 = fmaxf(v0, 0.f); v1 = fmaxf(v1, 0.f);
                v2 = fmaxf(v2, 0.f); v3 = fmaxf(v3, 0.f);
            }
            if (r0 < M)     store_pair(Cf, Ch, Cl, (size_t)r0 * N + col, v0, v1);
            if (r0 + 8 < M) store_pair(Cf, Ch, Cl, (size_t)(r0 + 8) * N + col, v2, v3);
        }
    }
}

// ---------------------------------------------------------------------------
// Fused GCN aggregation + residual + relu + bf16 split (byte-identical to R11)
// ---------------------------------------------------------------------------
__device__ __forceinline__ void f4_fma(float4& a, float w, const float4 v) {
    a.x = fmaf(w, v.x, a.x); a.y = fmaf(w, v.y, a.y);
    a.z = fmaf(w, v.z, a.z); a.w = fmaf(w, v.w, a.w);
}
__device__ __forceinline__ void split_store4(size_t base, float4 v) {
    float vv[4] = {v.x, v.y, v.z, v.w};
    __nv_bfloat16 hh[4], ll[4];
    #pragma unroll
    for (int i = 0; i < 4; i++) {
        hh[i] = __float2bfloat16(vv[i]);
        ll[i] = __float2bfloat16(vv[i] - __bfloat162float(hh[i]));
    }
    *(uint2*)(g_h_hi + base) = *(uint2*)hh;
    *(uint2*)(g_h_lo + base) = *(uint2*)ll;
}

__global__ __launch_bounds__(256) void gcn_agg_kernel(const float* __restrict__ convB) {
    int t = blockIdx.x * blockDim.x + threadIdx.x;
    int node = t >> 4;
    int lane = t & 15;
    if (node >= NN) return;

    float di = g_dinv[node];
    float w0 = di * di;
    const float4* mrow = (const float4*)(g_m + (size_t)node * HID);
    float4 a0 = mrow[lane], a1 = mrow[lane + 16], a2 = mrow[lane + 32];
    a0.x *= w0; a0.y *= w0; a0.z *= w0; a0.w *= w0;
    a1.x *= w0; a1.y *= w0; a1.z *= w0; a1.w *= w0;
    a2.x *= w0; a2.y *= w0; a2.z *= w0; a2.w *= w0;

    int beg = g_off[node], end = g_off[node + 1];
    for (int j = beg; j < end; j++) {
        int s = g_csr_src[j];
        float w = g_csr_w[j];
        const float4* ms = (const float4*)(g_m + (size_t)s * HID);
        f4_fma(a0, w, ms[lane]);
        f4_fma(a1, w, ms[lane + 16]);
        f4_fma(a2, w, ms[lane + 32]);
    }

    const float4* b4 = (const float4*)convB;
    float4 b0 = b4[lane], b1 = b4[lane + 16], b2 = b4[lane + 32];
    float4* hrow = (float4*)(g_h + (size_t)node * HID);
    float4 h0 = hrow[lane], h1 = hrow[lane + 16], h2 = hrow[lane + 32];
    h0.x += fmaxf(a0.x + b0.x, 0.f); h0.y += fmaxf(a0.y + b0.y, 0.f);
    h0.z += fmaxf(a0.z + b0.z, 0.f); h0.w += fmaxf(a0.w + b0.w, 0.f);
    h1.x += fmaxf(a1.x + b1.x, 0.f); h1.y += fmaxf(a1.y + b1.y, 0.f);
    h1.z += fmaxf(a1.z + b1.z, 0.f); h1.w += fmaxf(a1.w + b1.w, 0.f);
    h2.x += fmaxf(a2.x + b2.x, 0.f); h2.y += fmaxf(a2.y + b2.y, 0.f);
    h2.z += fmaxf(a2.z + b2.z, 0.f); h2.w += fmaxf(a2.w + b2.w, 0.f);
    hrow[lane] = h0; hrow[lane + 16] = h1; hrow[lane + 32] = h2;

    size_t base = (size_t)node * HID + lane * 4;
    split_store4(base, h0);
    split_store4(base + 64, h1);
    split_store4(base + 128, h2);
}

// ---------------------------------------------------------------------------
// Final head (unchanged)
// ---------------------------------------------------------------------------
__global__ void head_final_kernel(
    const float* __restrict__ Wp3, const float* __restrict__ bp3,
    const float* __restrict__ Wr2, const float* __restrict__ br2,
    float* __restrict__ out)
{
    int w = (blockIdx.x * blockDim.x + threadIdx.x) >> 5;
    int lane = threadIdx.x & 31;
    if (w >= NN) return;
    const float* p2 = g_p2 + (size_t)w * 96;
    const float* rr = g_r + (size_t)w * 96;
    float a0 = 0.0f, a1 = 0.0f, ar = 0.0f;
    #pragma unroll
    for (int i = lane; i < 96; i += 32) {
        float v = p2[i];
        a0 = fmaf(v, Wp3[i * 2 + 0], a0);
        a1 = fmaf(v, Wp3[i * 2 + 1], a1);
        ar = fmaf(rr[i], Wr2[i], ar);
    }
    #pragma unroll
    for (int o = 16; o; o >>= 1) {
        a0 += __shfl_down_sync(0xFFFFFFFFu, a0, o);
        a1 += __shfl_down_sync(0xFFFFFFFFu, a1, o);
        ar += __shfl_down_sync(0xFFFFFFFFu, ar, o);
    }
    if (lane == 0) {
        float p0 = a0 + bp3[0];
        float p1 = a1 + bp3[1];
        float rad = 1.0f / (1.0f + expf(-(ar + br2[0])));
        float nrm = sqrtf(p0 * p0 + p1 * p1) + 1e-8f;
        float scale = rad / nrm;
        out[w * 2 + 0] = p0 * scale;
        out[w * 2 + 1] = p1 * scale;
    }
}

// ---------------------------------------------------------------------------
extern "C" void kernel_launch(void* const* d_in, const int* in_sizes, int n_in,
                              void* d_out, int out_size)
{
    const float *x, *Wp, *bp, *convW, *convB, *Wp1, *bp1, *Wp2, *bp2, *Wp3, *bp3;
    const float *Wr1, *br1, *Wr2, *br2;
    const int *ei;

    if (in_sizes[0] == NN * DIN) {
        x     = (const float*)d_in[0];
        ei    = (const int*)  d_in[1];
        Wp    = (const float*)d_in[2];  bp    = (const float*)d_in[3];
        convW = (const float*)d_in[4];  convB = (const float*)d_in[5];
        Wp1   = (const float*)d_in[6];  bp1   = (const float*)d_in[7];
        Wp2   = (const float*)d_in[8];  bp2   = (const float*)d_in[9];
        Wp3   = (const float*)d_in[10]; bp3   = (const float*)d_in[11];
        Wr1   = (const float*)d_in[12]; br1   = (const float*)d_in[13];
        Wr2   = (const float*)d_in[14]; br2   = (const float*)d_in[15];
    } else {
        Wp    = (const float*)d_in[0];
        Wp1   = (const float*)d_in[1];
        Wp2   = (const float*)d_in[2];
        Wp3   = (const float*)d_in[3];
        Wr1   = (const float*)d_in[4];
        Wr2   = (const float*)d_in[5];
        bp    = (const float*)d_in[6];
        bp1   = (const float*)d_in[7];
        bp2   = (const float*)d_in[8];
        bp3   = (const float*)d_in[9];
        br1   = (const float*)d_in[10];
        br2   = (const float*)d_in[11];
        convB = (const float*)d_in[12];
        convW = (const float*)d_in[13];
        ei    = (const int*)  d_in[14];
        x     = (const float*)d_in[15];
    }
    float* out = (float*)d_out;

    float *p_h, *p_m, *p_p2, *p_r;
    __nv_bfloat16 *p_xh, *p_xl, *p_hh, *p_hl, *p_ph, *p_pl, *p_wh, *p_wl;
    cudaGetSymbolAddress((void**)&p_h,  g_h);
    cudaGetSymbolAddress((void**)&p_m,  g_m);
    cudaGetSymbolAddress((void**)&p_p2, g_p2);
    cudaGetSymbolAddress((void**)&p_r,  g_r);
    cudaGetSymbolAddress((void**)&p_xh, g_x_hi);
    cudaGetSymbolAddress((void**)&p_xl, g_x_lo);
    cudaGetSymbolAddress((void**)&p_hh, g_h_hi);
    cudaGetSymbolAddress((void**)&p_hl, g_h_lo);
    cudaGetSymbolAddress((void**)&p_ph, g_p_hi);
    cudaGetSymbolAddress((void**)&p_pl, g_p_lo);
    cudaGetSymbolAddress((void**)&p_wh, g_wt_hi);
    cudaGetSymbolAddress((void**)&p_wl, g_wt_lo);

    const int* src = ei;
    const int* dst = ei + NE;

    int nblk = (NN + 63) / 64;   // 782
    size_t sm192 = (size_t)3 * (64 + 192) * 128;  // 98304
    size_t sm96  = (size_t)3 * (64 + 96)  * 128;  // 61440
    cudaFuncSetAttribute((const void*)gemm_tc<192, 2, 4, 256>,
                         cudaFuncAttributeMaxDynamicSharedMemorySize, (int)sm192);
    cudaFuncSetAttribute((const void*)gemm_tc<96, 4, 2, 256>,
                         cudaFuncAttributeMaxDynamicSharedMemorySize, (int)sm96);

    // side stream + fork/join events for capture-legal overlap
    cudaStream_t s2;
    cudaStreamCreateWithFlags(&s2, cudaStreamNonBlocking);
    cudaEvent_t evFork, evCSR, evH, evR;
    cudaEventCreateWithFlags(&evFork, cudaEventDisableTiming);
    cudaEventCreateWithFlags(&evCSR,  cudaEventDisableTiming);
    cudaEventCreateWithFlags(&evH,    cudaEventDisableTiming);
    cudaEventCreateWithFlags(&evR,    cudaEventDisableTiming);

    // ---- main stream: operand prep + zero counters, then fork CSR build ----
    split_kernel<<<(NN * DIN + 255) / 256, 256>>>(x, p_xh, p_xl, NN * DIN);
    wprep_kernel<<<(OW_TOT + 255) / 256, 256>>>(Wp, convW, Wp1, Wp2, Wr1);
    zero_counts_kernel<<<(NN + 255) / 256, 256>>>();
    cudaEventRecord(evFork, 0);

    // ---- side stream: CSR build (only needed by agg0) ----
    cudaStreamWaitEvent(s2, evFork, 0);
    deg_count_kernel<<<(NE + 255) / 256, 256, 0, s2>>>(dst);
    scan1_kernel<<<SCAN_BLKS, 256, 0, s2>>>();
    scan2_kernel<<<1, 256, 0, s2>>>();
    scan3_kernel<<<SCAN_BLKS, 256, 0, s2>>>();
    dinv_kernel<<<(NN + 255) / 256, 256, 0, s2>>>();
    csr_fill_kernel<<<(NE + 255) / 256, 256, 0, s2>>>(src, dst);
    cudaEventRecord(evCSR, s2);

    // ---- main stream: proj GEMM + conv0 GEMM overlap the CSR build ----
    gemm_tc<192, 2, 4, 256><<<nblk, 256, sm192>>>(p_xh, p_xl, p_wh + OW_P,
                                                  p_wl + OW_P, bp, 0, p_h, p_hh, p_hl,
                                                  NN, DIN);
    gemm_tc<192, 2, 4, 256><<<nblk, 256, sm192>>>(p_hh, p_hl,
                                                  p_wh + OW_CONV,
                                                  p_wl + OW_CONV,
                                                  nullptr, 0, p_m, nullptr, nullptr,
                                                  NN, HID);
    cudaStreamWaitEvent(0, evCSR, 0);   // CSR must be ready before agg0
    gcn_agg_kernel<<<(NN * 16 + 255) / 256, 256>>>(convB);

    // layers 1..3 serial on main stream
    for (int l = 1; l < 4; l++) {
        gemm_tc<192, 2, 4, 256><<<nblk, 256, sm192>>>(p_hh, p_hl,
                                                      p_wh + OW_CONV + l * HID * HID,
                                                      p_wl + OW_CONV + l * HID * HID,
                                                      nullptr, 0, p_m, nullptr, nullptr,
                                                      NN, HID);
        gcn_agg_kernel<<<(NN * 16 + 255) / 256, 256>>>(convB + (size_t)l * HID);
    }

    // ---- heads: Wr1 forks onto the side stream, overlapping Wp1->Wp2 ----
    cudaEventRecord(evH, 0);
    cudaStreamWaitEvent(s2, evH, 0);
    gemm_tc<96, 4, 2, 256><<<nblk, 256, sm96, s2>>>(p_hh, p_hl, p_wh + OW_R1,
                                                    p_wl + OW_R1, br1, 1, p_r,
                                                    nullptr, nullptr, NN, HID);
    cudaEventRecord(evR, s2);

    gemm_tc<192, 2, 4, 256><<<nblk, 256, sm192>>>(p_hh, p_hl, p_wh + OW_P1, p_wl + OW_P1,
                                                  bp1, 1, nullptr, p_ph, p_pl, NN, HID);
    gemm_tc<96, 4, 2, 256><<<nblk, 256, sm96>>>(p_ph, p_pl, p_wh + OW_P2, p_wl + OW_P2,
                                                bp2, 1, p_p2, nullptr, nullptr, NN, HID);
    cudaStreamWaitEvent(0, evR, 0);     // join side stream before final head
    head_final_kernel<<<(NN * 32 + 255) / 256, 256>>>(Wp3, bp3, Wr2, br2, out);
}

// round 16
// speedup vs baseline: 1.1124x; 1.0653x over previous
#include <cuda_runtime.h>
#include <cuda_bf16.h>
#include <math.h>
#include <stdint.h>

#define NN 50000
#define NE 800000
#define DIN 128
#define HID 192
#define SCAN_BLKS 196

// ---- scratch (device globals; allocation APIs are forbidden) ----
__device__ float g_m[NN * HID];
__device__ float g_p2[NN * 96];
__device__ float g_r[NN * 96];
__device__ float g_dinv[NN];
__device__ int   g_degi[NN];
__device__ int   g_cur[NN];
__device__ int   g_off[NN + 1];
__device__ int   g_csr_src[NE];
__device__ float g_csr_w[NE];
__device__ int   g_bsum[SCAN_BLKS];
__device__ int   g_boff[SCAN_BLKS];

__device__ __nv_bfloat16 g_x_hi[NN * DIN], g_x_lo[NN * DIN];
__device__ __nv_bfloat16 g_h_hi[NN * HID], g_h_lo[NN * HID];   // h lives ONLY as splits
__device__ __nv_bfloat16 g_p_hi[NN * HID], g_p_lo[NN * HID];

#define OW_P    0
#define OW_CONV 24576
#define OW_P1   172032
#define OW_P2   208896
#define OW_R1   227328
#define OW_TOT  245760
__device__ __nv_bfloat16 g_wt_hi[OW_TOT], g_wt_lo[OW_TOT];

// ---------------------------------------------------------------------------
// Degree / CSR construction (byte-identical to R11/R15)
// ---------------------------------------------------------------------------
__global__ void zero_counts_kernel() {
    int i = blockIdx.x * blockDim.x + threadIdx.x;
    if (i < NN) { g_degi[i] = 0; g_cur[i] = 0; }
}
__global__ void deg_count_kernel(const int* __restrict__ dst) {
    int e = blockIdx.x * blockDim.x + threadIdx.x;
    if (e < NE) atomicAdd(&g_degi[dst[e]], 1);
}
__global__ void scan1_kernel() {
    __shared__ int s[256];
    int tid = threadIdx.x;
    int i = blockIdx.x * 256 + tid;
    int v = (i < NN) ? g_degi[i] : 0;
    s[tid] = v;
    __syncthreads();
    #pragma unroll
    for (int off = 1; off < 256; off <<= 1) {
        int t = (tid >= off) ? s[tid - off] : 0;
        __syncthreads();
        s[tid] += t;
        __syncthreads();
    }
    if (i < NN) g_off[i] = s[tid] - v;
    if (tid == 255) g_bsum[blockIdx.x] = s[255];
}
__global__ void scan2_kernel() {
    __shared__ int s[256];
    int tid = threadIdx.x;
    int v = (tid < SCAN_BLKS) ? g_bsum[tid] : 0;
    s[tid] = v;
    __syncthreads();
    #pragma unroll
    for (int off = 1; off < 256; off <<= 1) {
        int t = (tid >= off) ? s[tid - off] : 0;
        __syncthreads();
        s[tid] += t;
        __syncthreads();
    }
    if (tid < SCAN_BLKS) g_boff[tid] = s[tid] - v;
    if (tid == 0) g_off[NN] = s[255];
}
__global__ void scan3_kernel() {
    int i = blockIdx.x * 256 + threadIdx.x;
    if (i < NN) g_off[i] += g_boff[blockIdx.x];
}
__global__ void dinv_kernel() {
    int i = blockIdx.x * blockDim.x + threadIdx.x;
    if (i < NN) g_dinv[i] = rsqrtf((float)(g_degi[i] + 1));
}
__global__ void csr_fill_kernel(const int* __restrict__ src, const int* __restrict__ dst) {
    int e = blockIdx.x * blockDim.x + threadIdx.x;
    if (e >= NE) return;
    int s = src[e], d = dst[e];
    int pos = g_off[d] + atomicAdd(&g_cur[d], 1);
    g_csr_src[pos] = s;
    g_csr_w[pos] = g_dinv[s] * g_dinv[d];
}

// ---------------------------------------------------------------------------
// Operand prep (byte-identical to R15)
// ---------------------------------------------------------------------------
__global__ void split_kernel(const float* __restrict__ in,
                             __nv_bfloat16* __restrict__ oh,
                             __nv_bfloat16* __restrict__ ol, int n) {
    int i = blockIdx.x * blockDim.x + threadIdx.x;
    if (i >= n) return;
    float v = in[i];
    __nv_bfloat16 h = __float2bfloat16(v);
    oh[i] = h;
    ol[i] = __float2bfloat16(v - __bfloat162float(h));
}

__global__ void wprep_kernel(const float* __restrict__ Wp,
                             const float* __restrict__ convW,
                             const float* __restrict__ Wp1,
                             const float* __restrict__ Wp2,
                             const float* __restrict__ Wr1) {
    int idx = blockIdx.x * blockDim.x + threadIdx.x;
    if (idx >= OW_TOT) return;
    const float* src;
    int K, N, rel;
    if (idx < OW_CONV)      { rel = idx - OW_P;    src = Wp;  K = DIN; N = HID; }
    else if (idx < OW_P1)   { rel = idx - OW_CONV; src = convW + (rel / (HID * HID)) * (HID * HID);
                              rel %= HID * HID;    K = HID; N = HID; }
    else if (idx < OW_P2)   { rel = idx - OW_P1;   src = Wp1; K = HID; N = HID; }
    else if (idx < OW_R1)   { rel = idx - OW_P2;   src = Wp2; K = HID; N = 96;  }
    else                    { rel = idx - OW_R1;   src = Wr1; K = HID; N = 96;  }
    int n = rel / K, k = rel % K;
    float v = src[(size_t)k * N + n];
    __nv_bfloat16 h = __float2bfloat16(v);
    g_wt_hi[idx] = h;
    g_wt_lo[idx] = __float2bfloat16(v - __bfloat162float(h));
}

// ---------------------------------------------------------------------------
// Split-bf16 tensor-core GEMM — EXACT R11 configuration (banked).
// ---------------------------------------------------------------------------
#define MMA_BF16(d, a, b0_, b1_)                                              \
    asm volatile("mma.sync.aligned.m16n8k16.row.col.f32.bf16.bf16.f32 "       \
        "{%0,%1,%2,%3}, {%4,%5,%6,%7}, {%8,%9}, {%0,%1,%2,%3};"               \
        : "+f"((d)[0]), "+f"((d)[1]), "+f"((d)[2]), "+f"((d)[3])              \
        : "r"((a)[0]), "r"((a)[1]), "r"((a)[2]), "r"((a)[3]),                 \
          "r"(b0_), "r"(b1_))

#define LDSM_X4(r0, r1, r2, r3, addr)                                         \
    asm volatile("ldmatrix.sync.aligned.m8n8.x4.shared.b16 {%0,%1,%2,%3}, [%4];" \
        : "=r"(r0), "=r"(r1), "=r"(r2), "=r"(r3) : "r"(addr))

#define CP_A16(dst, src)                                                      \
    asm volatile("cp.async.cg.shared.global [%0], [%1], 16;"                  \
        :: "r"(dst), "l"(src))
#define CP_COMMIT() asm volatile("cp.async.commit_group;" ::: "memory")
#define CP_WAIT2()  asm volatile("cp.async.wait_group 2;" ::: "memory")
#define CP_WAIT1()  asm volatile("cp.async.wait_group 1;" ::: "memory")
#define CP_WAIT0()  asm volatile("cp.async.wait_group 0;" ::: "memory")

__device__ __forceinline__ uint32_t cvta_s(const void* p) {
    uint32_t a;
    asm("{ .reg .u64 t; cvta.to.shared.u64 t, %1; cvt.u32.u64 %0, t; }"
        : "=r"(a) : "l"(p));
    return a;
}

__device__ __forceinline__ void store_pair(
    float* Cf, __nv_bfloat16* Ch, __nv_bfloat16* Cl,
    size_t idx, float v0, float v1)
{
    if (Cf) *(float2*)(Cf + idx) = make_float2(v0, v1);
    if (Ch) {
        __nv_bfloat16 h0 = __float2bfloat16(v0), h1 = __float2bfloat16(v1);
        __nv_bfloat162 hp; hp.x = h0; hp.y = h1;
        *(__nv_bfloat162*)(Ch + idx) = hp;
        __nv_bfloat162 lp;
        lp.x = __float2bfloat16(v0 - __bfloat162float(h0));
        lp.y = __float2bfloat16(v1 - __bfloat162float(h1));
        *(__nv_bfloat162*)(Cl + idx) = lp;
    }
}

template <int N, int MW, int NW, int T>
__global__ __launch_bounds__(T, 2) void gemm_tc(
    const __nv_bfloat16* __restrict__ Ah, const __nv_bfloat16* __restrict__ Al,
    const __nv_bfloat16* __restrict__ Bh, const __nv_bfloat16* __restrict__ Bl,
    const float* __restrict__ bias, int relu,
    float* __restrict__ Cf, __nv_bfloat16* __restrict__ Ch,
    __nv_bfloat16* __restrict__ Cl, int M, int K)
{
    const int TM = 64;
    const int MF = TM / (16 * MW);
    const int NF = N / (8 * NW);
    const int A_BYTES = TM * 128;
    const int B_BYTES = N * 128;
    const int STAGE = A_BYTES + B_BYTES;
    const int NSTAGE = 3;

    extern __shared__ char smem[];
    uint32_t smem_u = cvta_s(smem);

    int tid = threadIdx.x, w = tid >> 5, lane = tid & 31;
    int row0 = blockIdx.x * TM;
    int mbase = (w % MW) * (MF * 16);
    int nbase = (w / MW) * (NF * 8);
    int lr = lane >> 2;
    int lc = (lane & 3) * 2;
    int lane7 = lane & 7;

    uint32_t aRow = (uint32_t)(((lane & 7) + 8 * ((lane >> 3) & 1)) * 128);
    uint32_t aC   = (uint32_t)(lane >> 4);
    uint32_t bRow = (uint32_t)(((lane & 7) + 8 * (lane >> 4)) * 128);
    uint32_t bC   = (uint32_t)((lane >> 3) & 1);

    float acc[MF][NF][4];
    #pragma unroll
    for (int a = 0; a < MF; a++)
        #pragma unroll
        for (int b = 0; b < NF; b++)
            #pragma unroll
            for (int c = 0; c < 4; c++) acc[a][b][c] = 0.0f;

    int nkc = K >> 5;

    auto load_tiles = [&](int st, int kc) {
        uint32_t base = smem_u + (uint32_t)(st * STAGE);
        for (int u = tid; u < TM * 8; u += T) {
            int r = u >> 3, c = u & 7;
            int gr = row0 + r;
            uint32_t dst = base + (uint32_t)(r << 7) + (uint32_t)(((c ^ (r & 7)) << 4));
            if (gr < M) {
                const __nv_bfloat16* s =
                    (c < 4 ? Ah : Al) + (size_t)gr * K + kc * 32 + (c & 3) * 8;
                CP_A16(dst, s);
            } else {
                asm volatile("st.shared.v4.b32 [%0], {%1,%1,%1,%1};"
                             :: "r"(dst), "r"(0u) : "memory");
            }
        }
        uint32_t bbase = base + (uint32_t)A_BYTES;
        for (int u = tid; u < N * 8; u += T) {
            int r = u >> 3, c = u & 7;
            uint32_t dst = bbase + (uint32_t)(r << 7) + (uint32_t)(((c ^ (r & 7)) << 4));
            const __nv_bfloat16* s =
                (c < 4 ? Bh : Bl) + (size_t)r * K + kc * 32 + (c & 3) * 8;
            CP_A16(dst, s);
        }
        CP_COMMIT();
    };

    int issued = 0;
    for (; issued < NSTAGE - 1 && issued < nkc; issued++)
        load_tiles(issued % NSTAGE, issued);

    for (int kc = 0; kc < nkc; kc++) {
        if (issued < nkc) { load_tiles(issued % NSTAGE, issued); issued++; }
        int pend = issued - kc - 1;
        if (pend >= 2) CP_WAIT2();
        else if (pend == 1) CP_WAIT1();
        else CP_WAIT0();
        __syncthreads();

        uint32_t aBase = smem_u + (uint32_t)((kc % NSTAGE) * STAGE);
        uint32_t bBase = aBase + (uint32_t)A_BYTES;

        #pragma unroll
        for (int ks = 0; ks < 2; ks++) {
            int c0h = 2 * ks;
            int c0l = 4 + 2 * ks;
            uint32_t ahf[MF][4], alf[MF][4];
            #pragma unroll
            for (int mf = 0; mf < MF; mf++) {
                uint32_t rowb = aBase + (uint32_t)((mbase + mf * 16) << 7) + aRow;
                LDSM_X4(ahf[mf][0], ahf[mf][1], ahf[mf][2], ahf[mf][3],
                        rowb + (uint32_t)((((int)(c0h + aC) ^ lane7) << 4)));
                LDSM_X4(alf[mf][0], alf[mf][1], alf[mf][2], alf[mf][3],
                        rowb + (uint32_t)((((int)(c0l + aC) ^ lane7) << 4)));
            }
            #pragma unroll
            for (int nf2 = 0; nf2 < NF / 2; nf2++) {
                uint32_t rowb = bBase + (uint32_t)((nbase + nf2 * 16) << 7) + bRow;
                uint32_t bh[4], bl[4];
                LDSM_X4(bh[0], bh[1], bh[2], bh[3],
                        rowb + (uint32_t)((((int)(c0h + bC) ^ lane7) << 4)));
                LDSM_X4(bl[0], bl[1], bl[2], bl[3],
                        rowb + (uint32_t)((((int)(c0l + bC) ^ lane7) << 4)));
                #pragma unroll
                for (int mf = 0; mf < MF; mf++) {
                    MMA_BF16(acc[mf][2 * nf2],     ahf[mf], bh[0], bh[1]);
                    MMA_BF16(acc[mf][2 * nf2],     ahf[mf], bl[0], bl[1]);
                    MMA_BF16(acc[mf][2 * nf2],     alf[mf], bh[0], bh[1]);
                    MMA_BF16(acc[mf][2 * nf2 + 1], ahf[mf], bh[2], bh[3]);
                    MMA_BF16(acc[mf][2 * nf2 + 1], ahf[mf], bl[2], bl[3]);
                    MMA_BF16(acc[mf][2 * nf2 + 1], alf[mf], bh[2], bh[3]);
                }
            }
        }
        __syncthreads();
    }

    #pragma unroll
    for (int mf = 0; mf < MF; mf++) {
        int r0 = row0 + mbase + mf * 16 + lr;
        #pragma unroll
        for (int nf = 0; nf < NF; nf++) {
            int col = nbase + nf * 8 + lc;
            float b0 = 0.0f, b1 = 0.0f;
            if (bias) { b0 = bias[col]; b1 = bias[col + 1]; }
            float v0 = acc[mf][nf][0] + b0, v1 = acc[mf][nf][1] + b1;
            float v2 = acc[mf][nf][2] + b0, v3 = acc[mf][nf][3] + b1;
            if (relu) {
                v0 = fmaxf(v0, 0.f); v1 = fmaxf(v1, 0.f);
                v2 = fmaxf(v2, 0.f); v3 = fmaxf(v3, 0.f);
            }
            if (r0 < M)     store_pair(Cf, Ch, Cl, (size_t)r0 * N + col, v0, v1);
            if (r0 + 8 < M) store_pair(Cf, Ch, Cl, (size_t)(r0 + 8) * N + col, v2, v3);
        }
    }
}

// ---------------------------------------------------------------------------
// Fused GCN aggregation + residual + relu.  h exists ONLY as bf16 hi/lo
// splits: residual is reconstructed as hi+lo (2^-16 exact) and re-split.
// Saves the 38MB/layer fp32 h write stream.
// ---------------------------------------------------------------------------
__device__ __forceinline__ void f4_fma(float4& a, float w, const float4 v) {
    a.x = fmaf(w, v.x, a.x); a.y = fmaf(w, v.y, a.y);
    a.z = fmaf(w, v.z, a.z); a.w = fmaf(w, v.w, a.w);
}
__device__ __forceinline__ float4 recon4(size_t base) {
    __nv_bfloat162 h01 = *(const __nv_bfloat162*)(g_h_hi + base);
    __nv_bfloat162 h23 = *(const __nv_bfloat162*)(g_h_hi + base + 2);
    __nv_bfloat162 l01 = *(const __nv_bfloat162*)(g_h_lo + base);
    __nv_bfloat162 l23 = *(const __nv_bfloat162*)(g_h_lo + base + 2);
    float4 r;
    r.x = __bfloat162float(h01.x) + __bfloat162float(l01.x);
    r.y = __bfloat162float(h01.y) + __bfloat162float(l01.y);
    r.z = __bfloat162float(h23.x) + __bfloat162float(l23.x);
    r.w = __bfloat162float(h23.y) + __bfloat162float(l23.y);
    return r;
}
__device__ __forceinline__ void split_store4(size_t base, float4 v) {
    float vv[4] = {v.x, v.y, v.z, v.w};
    __nv_bfloat16 hh[4], ll[4];
    #pragma unroll
    for (int i = 0; i < 4; i++) {
        hh[i] = __float2bfloat16(vv[i]);
        ll[i] = __float2bfloat16(vv[i] - __bfloat162float(hh[i]));
    }
    *(uint2*)(g_h_hi + base) = *(uint2*)hh;
    *(uint2*)(g_h_lo + base) = *(uint2*)ll;
}

__global__ __launch_bounds__(256) void gcn_agg_kernel(const float* __restrict__ convB) {
    int t = blockIdx.x * blockDim.x + threadIdx.x;
    int node = t >> 4;
    int lane = t & 15;
    if (node >= NN) return;

    float di = g_dinv[node];
    float w0 = di * di;
    const float4* mrow = (const float4*)(g_m + (size_t)node * HID);
    float4 a0 = mrow[lane], a1 = mrow[lane + 16], a2 = mrow[lane + 32];
    a0.x *= w0; a0.y *= w0; a0.z *= w0; a0.w *= w0;
    a1.x *= w0; a1.y *= w0; a1.z *= w0; a1.w *= w0;
    a2.x *= w0; a2.y *= w0; a2.z *= w0; a2.w *= w0;

    int beg = g_off[node], end = g_off[node + 1];
    for (int j = beg; j < end; j++) {
        int s = g_csr_src[j];
        float w = g_csr_w[j];
        const float4* ms = (const float4*)(g_m + (size_t)s * HID);
        f4_fma(a0, w, ms[lane]);
        f4_fma(a1, w, ms[lane + 16]);
        f4_fma(a2, w, ms[lane + 32]);
    }

    const float4* b4 = (const float4*)convB;
    float4 b0 = b4[lane], b1 = b4[lane + 16], b2 = b4[lane + 32];
    size_t base = (size_t)node * HID + lane * 4;
    float4 h0 = recon4(base), h1 = recon4(base + 64), h2 = recon4(base + 128);
    h0.x += fmaxf(a0.x + b0.x, 0.f); h0.y += fmaxf(a0.y + b0.y, 0.f);
    h0.z += fmaxf(a0.z + b0.z, 0.f); h0.w += fmaxf(a0.w + b0.w, 0.f);
    h1.x += fmaxf(a1.x + b1.x, 0.f); h1.y += fmaxf(a1.y + b1.y, 0.f);
    h1.z += fmaxf(a1.z + b1.z, 0.f); h1.w += fmaxf(a1.w + b1.w, 0.f);
    h2.x += fmaxf(a2.x + b2.x, 0.f); h2.y += fmaxf(a2.y + b2.y, 0.f);
    h2.z += fmaxf(a2.z + b2.z, 0.f); h2.w += fmaxf(a2.w + b2.w, 0.f);

    split_store4(base, h0);
    split_store4(base + 64, h1);
    split_store4(base + 128, h2);
}

// ---------------------------------------------------------------------------
// Final head (unchanged)
// ---------------------------------------------------------------------------
__global__ void head_final_kernel(
    const float* __restrict__ Wp3, const float* __restrict__ bp3,
    const float* __restrict__ Wr2, const float* __restrict__ br2,
    float* __restrict__ out)
{
    int w = (blockIdx.x * blockDim.x + threadIdx.x) >> 5;
    int lane = threadIdx.x & 31;
    if (w >= NN) return;
    const float* p2 = g_p2 + (size_t)w * 96;
    const float* rr = g_r + (size_t)w * 96;
    float a0 = 0.0f, a1 = 0.0f, ar = 0.0f;
    #pragma unroll
    for (int i = lane; i < 96; i += 32) {
        float v = p2[i];
        a0 = fmaf(v, Wp3[i * 2 + 0], a0);
        a1 = fmaf(v, Wp3[i * 2 + 1], a1);
        ar = fmaf(rr[i], Wr2[i], ar);
    }
    #pragma unroll
    for (int o = 16; o; o >>= 1) {
        a0 += __shfl_down_sync(0xFFFFFFFFu, a0, o);
        a1 += __shfl_down_sync(0xFFFFFFFFu, a1, o);
        ar += __shfl_down_sync(0xFFFFFFFFu, ar, o);
    }
    if (lane == 0) {
        float p0 = a0 + bp3[0];
        float p1 = a1 + bp3[1];
        float rad = 1.0f / (1.0f + expf(-(ar + br2[0])));
        float nrm = sqrtf(p0 * p0 + p1 * p1) + 1e-8f;
        float scale = rad / nrm;
        out[w * 2 + 0] = p0 * scale;
        out[w * 2 + 1] = p1 * scale;
    }
}

// ---------------------------------------------------------------------------
extern "C" void kernel_launch(void* const* d_in, const int* in_sizes, int n_in,
                              void* d_out, int out_size)
{
    const float *x, *Wp, *bp, *convW, *convB, *Wp1, *bp1, *Wp2, *bp2, *Wp3, *bp3;
    const float *Wr1, *br1, *Wr2, *br2;
    const int *ei;

    if (in_sizes[0] == NN * DIN) {
        x     = (const float*)d_in[0];
        ei    = (const int*)  d_in[1];
        Wp    = (const float*)d_in[2];  bp    = (const float*)d_in[3];
        convW = (const float*)d_in[4];  convB = (const float*)d_in[5];
        Wp1   = (const float*)d_in[6];  bp1   = (const float*)d_in[7];
        Wp2   = (const float*)d_in[8];  bp2   = (const float*)d_in[9];
        Wp3   = (const float*)d_in[10]; bp3   = (const float*)d_in[11];
        Wr1   = (const float*)d_in[12]; br1   = (const float*)d_in[13];
        Wr2   = (const float*)d_in[14]; br2   = (const float*)d_in[15];
    } else {
        Wp    = (const float*)d_in[0];
        Wp1   = (const float*)d_in[1];
        Wp2   = (const float*)d_in[2];
        Wp3   = (const float*)d_in[3];
        Wr1   = (const float*)d_in[4];
        Wr2   = (const float*)d_in[5];
        bp    = (const float*)d_in[6];
        bp1   = (const float*)d_in[7];
        bp2   = (const float*)d_in[8];
        bp3   = (const float*)d_in[9];
        br1   = (const float*)d_in[10];
        br2   = (const float*)d_in[11];
        convB = (const float*)d_in[12];
        convW = (const float*)d_in[13];
        ei    = (const int*)  d_in[14];
        x     = (const float*)d_in[15];
    }
    float* out = (float*)d_out;

    float *p_m, *p_p2, *p_r;
    __nv_bfloat16 *p_xh, *p_xl, *p_hh, *p_hl, *p_ph, *p_pl, *p_wh, *p_wl;
    cudaGetSymbolAddress((void**)&p_m,  g_m);
    cudaGetSymbolAddress((void**)&p_p2, g_p2);
    cudaGetSymbolAddress((void**)&p_r,  g_r);
    cudaGetSymbolAddress((void**)&p_xh, g_x_hi);
    cudaGetSymbolAddress((void**)&p_xl, g_x_lo);
    cudaGetSymbolAddress((void**)&p_hh, g_h_hi);
    cudaGetSymbolAddress((void**)&p_hl, g_h_lo);
    cudaGetSymbolAddress((void**)&p_ph, g_p_hi);
    cudaGetSymbolAddress((void**)&p_pl, g_p_lo);
    cudaGetSymbolAddress((void**)&p_wh, g_wt_hi);
    cudaGetSymbolAddress((void**)&p_wl, g_wt_lo);

    const int* src = ei;
    const int* dst = ei + NE;

    int nblk = (NN + 63) / 64;   // 782
    size_t sm192 = (size_t)3 * (64 + 192) * 128;  // 98304
    size_t sm96  = (size_t)3 * (64 + 96)  * 128;  // 61440
    cudaFuncSetAttribute((const void*)gemm_tc<192, 2, 4, 256>,
                         cudaFuncAttributeMaxDynamicSharedMemorySize, (int)sm192);
    cudaFuncSetAttribute((const void*)gemm_tc<96, 4, 2, 256>,
                         cudaFuncAttributeMaxDynamicSharedMemorySize, (int)sm96);

    // side stream + fork/join events for capture-legal overlap
    cudaStream_t s2;
    cudaStreamCreateWithFlags(&s2, cudaStreamNonBlocking);
    cudaEvent_t evFork, evCSR, evH, evR;
    cudaEventCreateWithFlags(&evFork, cudaEventDisableTiming);
    cudaEventCreateWithFlags(&evCSR,  cudaEventDisableTiming);
    cudaEventCreateWithFlags(&evH,    cudaEventDisableTiming);
    cudaEventCreateWithFlags(&evR,    cudaEventDisableTiming);

    // ---- main stream: operand prep + zero counters, then fork CSR build ----
    split_kernel<<<(NN * DIN + 255) / 256, 256>>>(x, p_xh, p_xl, NN * DIN);
    wprep_kernel<<<(OW_TOT + 255) / 256, 256>>>(Wp, convW, Wp1, Wp2, Wr1);
    zero_counts_kernel<<<(NN + 255) / 256, 256>>>();
    cudaEventRecord(evFork, 0);

    // ---- side stream: CSR build (only needed by agg0) ----
    cudaStreamWaitEvent(s2, evFork, 0);
    deg_count_kernel<<<(NE + 255) / 256, 256, 0, s2>>>(dst);
    scan1_kernel<<<SCAN_BLKS, 256, 0, s2>>>();
    scan2_kernel<<<1, 256, 0, s2>>>();
    scan3_kernel<<<SCAN_BLKS, 256, 0, s2>>>();
    dinv_kernel<<<(NN + 255) / 256, 256, 0, s2>>>();
    csr_fill_kernel<<<(NE + 255) / 256, 256, 0, s2>>>(src, dst);
    cudaEventRecord(evCSR, s2);

    // ---- main stream: proj GEMM (splits only) + conv0 GEMM overlap CSR ----
    gemm_tc<192, 2, 4, 256><<<nblk, 256, sm192>>>(p_xh, p_xl, p_wh + OW_P,
                                                  p_wl + OW_P, bp, 0,
                                                  nullptr, p_hh, p_hl, NN, DIN);
    gemm_tc<192, 2, 4, 256><<<nblk, 256, sm192>>>(p_hh, p_hl,
                                                  p_wh + OW_CONV,
                                                  p_wl + OW_CONV,
                                                  nullptr, 0, p_m, nullptr, nullptr,
                                                  NN, HID);
    cudaStreamWaitEvent(0, evCSR, 0);   // CSR must be ready before agg0
    gcn_agg_kernel<<<(NN * 16 + 255) / 256, 256>>>(convB);

    // layers 1..3 serial on main stream
    for (int l = 1; l < 4; l++) {
        gemm_tc<192, 2, 4, 256><<<nblk, 256, sm192>>>(p_hh, p_hl,
                                                      p_wh + OW_CONV + l * HID * HID,
                                                      p_wl + OW_CONV + l * HID * HID,
                                                      nullptr, 0, p_m, nullptr, nullptr,
                                                      NN, HID);
        gcn_agg_kernel<<<(NN * 16 + 255) / 256, 256>>>(convB + (size_t)l * HID);
    }

    // ---- heads: Wr1 forks onto the side stream, overlapping Wp1->Wp2 ----
    cudaEventRecord(evH, 0);
    cudaStreamWaitEvent(s2, evH, 0);
    gemm_tc<96, 4, 2, 256><<<nblk, 256, sm96, s2>>>(p_hh, p_hl, p_wh + OW_R1,
                                                    p_wl + OW_R1, br1, 1, p_r,
                                                    nullptr, nullptr, NN, HID);
    cudaEventRecord(evR, s2);

    gemm_tc<192, 2, 4, 256><<<nblk, 256, sm192>>>(p_hh, p_hl, p_wh + OW_P1, p_wl + OW_P1,
                                                  bp1, 1, nullptr, p_ph, p_pl, NN, HID);
    gemm_tc<96, 4, 2, 256><<<nblk, 256, sm96>>>(p_ph, p_pl, p_wh + OW_P2, p_wl + OW_P2,
                                                bp2, 1, p_p2, nullptr, nullptr, NN, HID);
    cudaStreamWaitEvent(0, evR, 0);     // join side stream before final head
    head_final_kernel<<<(NN * 32 + 255) / 256, 256>>>(Wp3, bp3, Wr2, br2, out);
}